// round 14
// baseline (speedup 1.0000x reference)
#include <cuda_runtime.h>
#include <math.h>

// Problem constants (fixed by the dataset instance)
#define BATCH   8
#define NP      4096
#define FDIM    512
#define H1DIM   256
#define H2DIM   128
#define DDIM    6

#define FSCORE_W 0.1f
#define TASK_W   1.0f
#define DOMAIN_W 0.1f
#define INV_C    5000.0f       // 1/(2*sigma^2)

// z-bucket grid for ordering only (exactness never relies on bucket width).
#define NB      256
#define BMIN    (-6.0f)
#define INV_BW  (NB / 12.0f)

#define TPB     128
#define PPT     2
#define QPB     (TPB*PPT)      // 256 queries per chamfer block
#define NQB     (NP/QPB)       // 16
#define NTILE   32             // key tiles of 128
#define JPT     64             // packed key-pairs per tile
#define NARRIVE (NQB*2*BATCH + BATCH)   // 256 chamfer + 8 domain = 264

// Scratch (device globals; every slot written unconditionally each launch).
__device__ float4     g_q4[2][BATCH][NP];      // z-ordered (x,y,z,0)
__device__ ulonglong2 g_pA[2][BATCH][NP/2];    // {-2x pair},{-2y pair}
__device__ ulonglong2 g_pB[2][BATCH][NP/2];    // {-2z pair},{|k|^2 pair}
__device__ int        g_start[2][BATCH][NB];
__device__ float      g_sufmin[2][BATCH][NTILE];  // min z over tiles >= t
__device__ float      g_premax[2][BATCH][NTILE];  // max z over tiles <= t
__device__ float      g_r3[2][BATCH][NQB][2];  // per-block (sum_d, sum_exp)
__device__ float      g_dom[BATCH];
__device__ int        g_ctr = 0;               // zero-init; self-resetting

// ---------------- f32x2 helpers (sm_100+ packed fp32) ----------------
__device__ __forceinline__ unsigned long long pack2(float lo, float hi) {
    unsigned long long r;
    asm("mov.b64 %0, {%1, %2};" : "=l"(r) : "f"(lo), "f"(hi));
    return r;
}
__device__ __forceinline__ unsigned long long fma2(unsigned long long a,
                                                   unsigned long long b,
                                                   unsigned long long c) {
    unsigned long long r;
    asm("fma.rn.f32x2 %0, %1, %2, %3;" : "=l"(r) : "l"(a), "l"(b), "l"(c));
    return r;
}
__device__ __forceinline__ float2 unpack2(unsigned long long v) {
    float2 f;
    asm("mov.b64 {%0, %1}, %2;" : "=f"(f.x), "=f"(f.y) : "l"(v));
    return f;
}
__device__ __forceinline__ unsigned fenc(float f) {
    unsigned u = __float_as_uint(f);
    return (u & 0x80000000u) ? ~u : (u | 0x80000000u);
}
__device__ __forceinline__ float fdec(unsigned u) {
    unsigned v = (u & 0x80000000u) ? (u & 0x7fffffffu) : ~u;
    return __uint_as_float(v);
}

// ============================ Launch 1 ============================
// One 512-thread block per (cloud, batch): histogram z -> prefix -> scatter
// into z-bucket order -> pack FFMA2 key pairs -> exact per-tile z stats.
__global__ __launch_bounds__(512) void bucket_kernel(
    const float* __restrict__ P, const float* __restrict__ T)
{
    __shared__ int cnt[NB];
    __shared__ int inc[NB];
    __shared__ int tmp[NB];
    __shared__ int boff[NB];
    __shared__ unsigned tzmin[NTILE], tzmax[NTILE];

    const int tid   = threadIdx.x;
    const int cloud = blockIdx.x & 1;
    const int b     = blockIdx.x >> 1;
    const float* src = cloud ? (T + (size_t)b * NP * 3)
                             : (P + (size_t)b * NP * 3);

    if (tid < NB) cnt[tid] = 0;
    if (tid < NTILE) { tzmin[tid] = 0xFFFFFFFFu; tzmax[tid] = 0u; }
    __syncthreads();
    for (int i = tid; i < NP; i += 512) {
        float z = src[i * 3 + 2];
        int bk = min(max((int)((z - BMIN) * INV_BW), 0), NB - 1);
        atomicAdd(&cnt[bk], 1);
    }
    __syncthreads();
    if (tid < NB) inc[tid] = cnt[tid];
    __syncthreads();
    #pragma unroll
    for (int d = 1; d < NB; d <<= 1) {
        if (tid < NB) tmp[tid] = (tid >= d) ? inc[tid - d] + inc[tid] : inc[tid];
        __syncthreads();
        if (tid < NB) inc[tid] = tmp[tid];
        __syncthreads();
    }
    if (tid < NB) {
        boff[tid] = inc[tid] - cnt[tid];   // exclusive prefix
        cnt[tid] = 0;                      // reuse as scatter cursor
    }
    __syncthreads();

    for (int i = tid; i < NP; i += 512) {
        float x = src[i * 3 + 0];
        float y = src[i * 3 + 1];
        float z = src[i * 3 + 2];
        int bk = min(max((int)((z - BMIN) * INV_BW), 0), NB - 1);
        int pos = boff[bk] + atomicAdd(&cnt[bk], 1);
        g_q4[cloud][b][pos] = make_float4(x, y, z, 0.0f);
    }
    if (tid < NB) g_start[cloud][b][tid] = boff[tid];
    __syncthreads();   // g_q4 writes visible block-wide

    for (int j = tid; j < NP / 2; j += 512) {
        float4 k0 = g_q4[cloud][b][2 * j];
        float4 k1 = g_q4[cloud][b][2 * j + 1];
        ulonglong2 A, B;
        A.x = pack2(-2.0f * k0.x, -2.0f * k1.x);
        A.y = pack2(-2.0f * k0.y, -2.0f * k1.y);
        B.x = pack2(-2.0f * k0.z, -2.0f * k1.z);
        B.y = pack2(k0.x * k0.x + k0.y * k0.y + k0.z * k0.z,
                    k1.x * k1.x + k1.y * k1.y + k1.z * k1.z);
        g_pA[cloud][b][j] = A;
        g_pB[cloud][b][j] = B;
        int t = j >> 6;   // 64 pairs per tile
        unsigned e0 = fenc(k0.z), e1 = fenc(k1.z);
        atomicMin(&tzmin[t], min(e0, e1));
        atomicMax(&tzmax[t], max(e0, e1));
    }
    __syncthreads();
    if (tid == 0) {
        float run = 1e30f;
        for (int t = NTILE - 1; t >= 0; t--) {
            run = fminf(run, fdec(tzmin[t]));
            g_sufmin[cloud][b][t] = run;
        }
    }
    if (tid == 1) {
        float run = -1e30f;
        for (int t = 0; t < NTILE; t++) {
            run = fmaxf(run, fdec(tzmax[t]));
            g_premax[cloud][b][t] = run;
        }
    }
}

// ---------------- domain MLP (rides in the chamfer launch) ----------------
__device__ __forceinline__ void domain_block(
    int b, int tid,
    const float* __restrict__ X,
    const float* __restrict__ W1, const float* __restrict__ b1,
    const float* __restrict__ W2, const float* __restrict__ b2,
    const float* __restrict__ W3, const float* __restrict__ b3,
    const int* __restrict__ labels)
{
    __shared__ float xs[FDIM];
    __shared__ float h1[H1DIM];
    __shared__ float h2[H2DIM];
    __shared__ float lg[DDIM];

    for (int i = tid; i < FDIM; i += TPB) xs[i] = X[b * FDIM + i];
    __syncthreads();
    {
        float a0 = b1[tid], a1 = b1[tid + 128];
        #pragma unroll 8
        for (int f = 0; f < FDIM; f++) {
            float x = xs[f];
            a0 = fmaf(x, W1[f * H1DIM + tid],       a0);
            a1 = fmaf(x, W1[f * H1DIM + tid + 128], a1);
        }
        h1[tid]       = fmaxf(a0, 0.0f);
        h1[tid + 128] = fmaxf(a1, 0.0f);
    }
    __syncthreads();
    {
        float a = b2[tid];
        #pragma unroll 8
        for (int k = 0; k < H1DIM; k++)
            a = fmaf(h1[k], W2[k * H2DIM + tid], a);
        h2[tid] = fmaxf(a, 0.0f);
    }
    __syncthreads();
    if (tid < DDIM) {
        float a = b3[tid];
        #pragma unroll 8
        for (int k = 0; k < H2DIM; k++)
            a = fmaf(h2[k], W3[k * DDIM + tid], a);
        lg[tid] = a;
    }
    __syncthreads();
    if (tid == 0) {
        float mx = lg[0];
        for (int d = 1; d < DDIM; d++) mx = fmaxf(mx, lg[d]);
        float se = 0.f;
        for (int d = 0; d < DDIM; d++) se += expf(lg[d] - mx);
        g_dom[b] = (mx + logf(se)) - lg[labels[b]];
    }
    __syncthreads();
}

// Final combine (32 threads of whichever block arrives last).
__device__ __forceinline__ void final_combine(
    const float* __restrict__ dsw, float* __restrict__ out, int t)
{
    float sA = 0.f, sEA = 0.f, sB = 0.f, sEB = 0.f;
    float dwc = 0.f, domc = 0.f;
    if (t < BATCH) {
        #pragma unroll
        for (int c = 0; c < NQB; c++) {
            sA  += g_r3[0][t][c][0];
            sEA += g_r3[0][t][c][1];
            sB  += g_r3[1][t][c][0];
            sEB += g_r3[1][t][c][1];
        }
        const float invN = 1.0f / (float)NP;
        float ch_i = sA * invN + sB * invN;
        float p_i  = sEA * invN;
        float r_i  = sEB * invN;
        float f_i  = 2.0f * p_i * r_i / (p_i + r_i + 1e-8f);
        float loss_i = ch_i + FSCORE_W * (1.0f - f_i);
        dwc  = dsw[t] * loss_i;
        domc = g_dom[t];
    }
    #pragma unroll
    for (int s = 16; s > 0; s >>= 1) {
        sA   += __shfl_xor_sync(0xffffffffu, sA,   s);
        sEA  += __shfl_xor_sync(0xffffffffu, sEA,  s);
        sB   += __shfl_xor_sync(0xffffffffu, sB,   s);
        sEB  += __shfl_xor_sync(0xffffffffu, sEB,  s);
        dwc  += __shfl_xor_sync(0xffffffffu, dwc,  s);
        domc += __shfl_xor_sync(0xffffffffu, domc, s);
    }
    if (t == 0) {
        const float invBN = 1.0f / (float)(BATCH * NP);
        float chamfer = sA * invBN + sB * invBN;
        float prec = sEA * invBN;
        float rec  = sEB * invBN;
        float fscore = 2.0f * prec * rec / (prec + rec + 1e-8f);
        float task = chamfer + FSCORE_W * (1.0f - fscore);
        out[0] = TASK_W * task + DOMAIN_W * (domc / (float)BATCH)
               + (dwc / (float)BATCH);
    }
}

__device__ __forceinline__ void global_arrive(
    const float* __restrict__ dsw, float* __restrict__ out, int tid,
    int* sh_final)
{
    __threadfence();
    if (tid == 0) {
        int old = atomicAdd(&g_ctr, 1);
        *sh_final = (old == NARRIVE - 1) ? 1 : 0;
        if (*sh_final) atomicExch(&g_ctr, 0);   // reset for graph replay
    }
    __syncthreads();
    if (*sh_final && tid < 32) final_combine(dsw, out, tid);
}

// ============================ Launch 2 ============================
// Two-phase static-window chamfer:
//   Phase 1: scan the 2 rank-matched key tiles (both clouds z-sorted, same
//            N => similar z) -> every query holds a finite best.
//   One block reduction -> bb = max over the block's queries of current
//            best (upper bound on every final best).
//   Static range via suffix-min/prefix-max tile z-bounds (monotone =>
//            first skippable tile proves all beyond it skippable; skipped
//            tile keys are >= sqrt(bb) from every query => EXACT).
//   Phase 2: double-buffered pipelined scan of the tile list -- no per-tile
//            reductions, no breaks, no extra syncs.
__global__ __launch_bounds__(TPB) void chamfer_kernel(
    const float* __restrict__ X,
    const float* __restrict__ W1, const float* __restrict__ b1,
    const float* __restrict__ W2, const float* __restrict__ b2,
    const float* __restrict__ W3, const float* __restrict__ b3,
    const int* __restrict__ labels,
    const float* __restrict__ dsw, float* __restrict__ out)
{
    __shared__ int sh_final;
    const int tid = threadIdx.x;
    const int b   = blockIdx.z;

    if (blockIdx.y == 2) {
        if (blockIdx.x == 0) {
            domain_block(b, tid, X, W1, b1, W2, b2, W3, b3, labels);
            global_arrive(dsw, out, tid, &sh_final);
        }
        return;
    }

    __shared__ ulonglong2 sAb[2][JPT], sBb[2][JPT];
    __shared__ float ssuf[NTILE], spre[NTILE];
    __shared__ float rmm[4][2];
    __shared__ float bbw[4];
    __shared__ float red[4][2];
    __shared__ int   sh_list[NTILE];
    __shared__ int   sh_n;

    const int qb   = blockIdx.x;
    const int dir  = blockIdx.y;
    const int kc   = 1 - dir;
    const int lane = tid & 31;
    const int w    = tid >> 5;

    // load + pack queries; block z-range
    unsigned long long qxd[PPT], qyd[PPT], qzd[PPT];
    float q2[PPT], emin[PPT];
    float zmn = 1e30f, zmx = -1e30f;
    #pragma unroll
    for (int p = 0; p < PPT; p++) {
        int pos = qb * QPB + p * TPB + tid;
        float4 qq = g_q4[dir][b][pos];
        qxd[p] = pack2(qq.x, qq.x);
        qyd[p] = pack2(qq.y, qq.y);
        qzd[p] = pack2(qq.z, qq.z);
        q2[p]  = qq.x * qq.x + qq.y * qq.y + qq.z * qq.z;
        emin[p] = 1e30f;
        zmn = fminf(zmn, qq.z);
        zmx = fmaxf(zmx, qq.z);
    }
    if (tid < NTILE) {
        ssuf[tid] = g_sufmin[kc][b][tid];
        spre[tid] = g_premax[kc][b][tid];
    }
    #pragma unroll
    for (int s = 16; s > 0; s >>= 1) {
        zmn = fminf(zmn, __shfl_xor_sync(0xffffffffu, zmn, s));
        zmx = fmaxf(zmx, __shfl_xor_sync(0xffffffffu, zmx, s));
    }
    if (lane == 0) { rmm[w][0] = zmn; rmm[w][1] = zmx; }
    __syncthreads();
    const float qzmin = fminf(fminf(rmm[0][0], rmm[1][0]),
                              fminf(rmm[2][0], rmm[3][0]));
    const float qzmax = fmaxf(fmaxf(rmm[0][1], rmm[1][1]),
                              fmaxf(rmm[2][1], rmm[3][1]));

    const int s0 = qb * 2;   // rank-matched seed tiles: s0, s0+1

    // ---------- phase 1: seed scan (2 tiles, simple load/compute) ----------
    #pragma unroll
    for (int tt = 0; tt < 2; tt++) {
        int t = s0 + tt;
        if (tid < JPT) sAb[0][tid] = g_pA[kc][b][t * JPT + tid];
        else           sBb[0][tid - JPT] = g_pB[kc][b][t * JPT + tid - JPT];
        __syncthreads();
        #pragma unroll 8
        for (int j = 0; j < JPT; j++) {
            ulonglong2 A = sAb[0][j];
            ulonglong2 B = sBb[0][j];
            #pragma unroll
            for (int p = 0; p < PPT; p++) {
                unsigned long long e = fma2(qxd[p], A.x, B.y);
                e = fma2(qyd[p], A.y, e);
                e = fma2(qzd[p], B.x, e);
                float2 ef = unpack2(e);
                emin[p] = fminf(emin[p], fminf(ef.x, ef.y));
            }
        }
        __syncthreads();
    }

    // ---------- one reduction: bb = block max of current bests ----------
    {
        float bd = fmaxf(emin[0] + q2[0], emin[1] + q2[1]);
        #pragma unroll
        for (int s = 16; s > 0; s >>= 1)
            bd = fmaxf(bd, __shfl_xor_sync(0xffffffffu, bd, s));
        if (lane == 0) bbw[w] = bd;
    }
    __syncthreads();

    // ---------- static tile list (thread 0) ----------
    if (tid == 0) {
        float bbv = fmaxf(fmaxf(bbw[0], bbw[1]), fmaxf(bbw[2], bbw[3]));
        int n = 0;
        for (int t = s0 + 2; t < NTILE; t++) {           // rightward
            float g = ssuf[t] - qzmax;
            if (g > 0.0f && g * g >= bbv) break;
            sh_list[n++] = t;
        }
        for (int t = s0 - 1; t >= 0; t--) {              // leftward
            float g = qzmin - spre[t];
            if (g > 0.0f && g * g >= bbv) break;
            sh_list[n++] = t;
        }
        sh_n = n;
    }
    __syncthreads();
    const int n = sh_n;

    // ---------- phase 2: static double-buffered scan of the list ----------
    if (n > 0) {
        {
            int t = sh_list[0];
            if (tid < JPT) sAb[0][tid] = g_pA[kc][b][t * JPT + tid];
            else           sBb[0][tid - JPT] = g_pB[kc][b][t * JPT + tid - JPT];
        }
        __syncthreads();
        for (int i = 0; i < n; i++) {
            const int buf = i & 1;
            ulonglong2 pre;
            if (i + 1 < n) {
                int t = sh_list[i + 1];
                pre = (tid < JPT) ? g_pA[kc][b][t * JPT + tid]
                                  : g_pB[kc][b][t * JPT + tid - JPT];
            }
            #pragma unroll 8
            for (int j = 0; j < JPT; j++) {
                ulonglong2 A = sAb[buf][j];   // LDS.128 broadcast
                ulonglong2 B = sBb[buf][j];
                #pragma unroll
                for (int p = 0; p < PPT; p++) {
                    unsigned long long e = fma2(qxd[p], A.x, B.y);
                    e = fma2(qyd[p], A.y, e);
                    e = fma2(qzd[p], B.x, e);
                    float2 ef = unpack2(e);
                    emin[p] = fminf(emin[p], fminf(ef.x, ef.y));
                }
            }
            if (i + 1 < n) {
                if (tid < JPT) sAb[buf ^ 1][tid] = pre;
                else           sBb[buf ^ 1][tid - JPT] = pre;
            }
            __syncthreads();
        }
    }

    // ---------- epilogue: block (sum_d, sum_exp) ----------
    {
        float d0 = emin[0] + q2[0];
        float d1 = emin[1] + q2[1];
        float sd = d0 + d1;
        float se = __expf(-d0 * INV_C) + __expf(-d1 * INV_C);
        #pragma unroll
        for (int s = 16; s > 0; s >>= 1) {
            sd += __shfl_xor_sync(0xffffffffu, sd, s);
            se += __shfl_xor_sync(0xffffffffu, se, s);
        }
        if (lane == 0) { red[w][0] = sd; red[w][1] = se; }
        __syncthreads();
        if (tid == 0) {
            g_r3[dir][b][qb][0] = red[0][0] + red[1][0] + red[2][0] + red[3][0];
            g_r3[dir][b][qb][1] = red[0][1] + red[1][1] + red[2][1] + red[3][1];
        }
    }

    global_arrive(dsw, out, tid, &sh_final);
}

extern "C" void kernel_launch(void* const* d_in, const int* in_sizes, int n_in,
                              void* d_out, int out_size)
{
    const float* pred_pc   = (const float*)d_in[0];
    const float* target_pc = (const float*)d_in[1];
    const float* dfeat     = (const float*)d_in[2];
    const float* dsw       = (const float*)d_in[3];
    const float* W1 = (const float*)d_in[4];
    const float* b1 = (const float*)d_in[5];
    const float* W2 = (const float*)d_in[6];
    const float* b2 = (const float*)d_in[7];
    const float* W3 = (const float*)d_in[8];
    const float* b3 = (const float*)d_in[9];
    const int*   labels = (const int*)d_in[10];
    float* out = (float*)d_out;

    bucket_kernel<<<16, 512>>>(pred_pc, target_pc);

    // (16, 3, 8): y<2 chamfer dirs; y==2,x==0 domain blocks.
    dim3 grid(NQB, 3, BATCH);
    chamfer_kernel<<<grid, TPB>>>(dfeat, W1, b1, W2, b2, W3, b3,
                                  labels, dsw, out);
}

// round 15
// speedup vs baseline: 1.4752x; 1.4752x over previous
#include <cuda_runtime.h>
#include <math.h>

// Problem constants (fixed by the dataset instance)
#define BATCH   8
#define NP      4096
#define FDIM    512
#define H1DIM   256
#define H2DIM   128
#define DDIM    6

#define FSCORE_W 0.1f
#define TASK_W   1.0f
#define DOMAIN_W 0.1f
#define INV_C    5000.0f       // 1/(2*sigma^2)

// Chamfer tiling
#define TPB     128
#define PPT     8
#define QTILE   (TPB*PPT)      // 1024 queries per block
#define QB      (NP/QTILE)     // 4
#define KSPLIT  8
#define KCHUNK  (NP/KSPLIT)    // 512 keys per block
#define KTILE   128            // keys per shared tile
#define NTILES  (KCHUNK/KTILE) // 4

#define NGROUPS (2*BATCH*QB)           // 64 chamfer groups
#define NARRIVE (NGROUPS + BATCH)      // + 8 domain blocks = 72

// Scratch (device globals; data slots written unconditionally each launch).
__device__ float g_pmin[2][BATCH][KSPLIT][NP];  // per-split partial mins
__device__ float g_r3[2][BATCH][QB][2];         // per-group (sum_d, sum_exp)
__device__ float g_dom[BATCH];
__device__ int   g_ctr_q[2][BATCH][QB];         // zero-init; self-resetting
__device__ int   g_ctr = 0;                     // zero-init; self-resetting

// ---------------- f32x2 helpers (sm_100+ packed fp32) ----------------
__device__ __forceinline__ unsigned long long pack2(float lo, float hi) {
    unsigned long long r;
    asm("mov.b64 %0, {%1, %2};" : "=l"(r) : "f"(lo), "f"(hi));
    return r;
}
__device__ __forceinline__ unsigned long long fma2(unsigned long long a,
                                                   unsigned long long b,
                                                   unsigned long long c) {
    unsigned long long r;
    asm("fma.rn.f32x2 %0, %1, %2, %3;" : "=l"(r) : "l"(a), "l"(b), "l"(c));
    return r;
}
__device__ __forceinline__ float2 unpack2(unsigned long long v) {
    float2 f;
    asm("mov.b64 {%0, %1}, %2;" : "=f"(f.x), "=f"(f.y) : "l"(v));
    return f;
}

// Shared: double-buffered packed key tiles (chamfer path).
__shared__ float sA[2][KTILE * 2];
__shared__ float sB[2][KTILE * 2];
// Shared: domain path (distinct blocks).
__shared__ float xs[FDIM];
__shared__ float h1[H1DIM];
__shared__ float h2[H2DIM];
__shared__ float lg[DDIM];
// Shared: epilogue flags/reductions.
__shared__ float red2[4][2];
__shared__ int   sh_last, sh_final;

// Final combine (32 threads of whichever block arrives last).
__device__ __forceinline__ void final_combine(
    const float* __restrict__ dsw, float* __restrict__ out, int t)
{
    float sA_ = 0.f, sEA = 0.f, sB_ = 0.f, sEB = 0.f;
    float dwc = 0.f, domc = 0.f;
    if (t < BATCH) {
        #pragma unroll
        for (int qb = 0; qb < QB; qb++) {
            sA_ += g_r3[0][t][qb][0];
            sEA += g_r3[0][t][qb][1];
            sB_ += g_r3[1][t][qb][0];
            sEB += g_r3[1][t][qb][1];
        }
        const float invN = 1.0f / (float)NP;
        float ch_i = sA_ * invN + sB_ * invN;
        float p_i  = sEA * invN;
        float r_i  = sEB * invN;
        float f_i  = 2.0f * p_i * r_i / (p_i + r_i + 1e-8f);
        float loss_i = ch_i + FSCORE_W * (1.0f - f_i);
        dwc  = dsw[t] * loss_i;
        domc = g_dom[t];
    }
    #pragma unroll
    for (int s = 16; s > 0; s >>= 1) {
        sA_  += __shfl_xor_sync(0xffffffffu, sA_,  s);
        sEA  += __shfl_xor_sync(0xffffffffu, sEA,  s);
        sB_  += __shfl_xor_sync(0xffffffffu, sB_,  s);
        sEB  += __shfl_xor_sync(0xffffffffu, sEB,  s);
        dwc  += __shfl_xor_sync(0xffffffffu, dwc,  s);
        domc += __shfl_xor_sync(0xffffffffu, domc, s);
    }
    if (t == 0) {
        const float invBN = 1.0f / (float)(BATCH * NP);
        float chamfer = sA_ * invBN + sB_ * invBN;
        float prec = sEA * invBN;
        float rec  = sEB * invBN;
        float fscore = 2.0f * prec * rec / (prec + rec + 1e-8f);
        float task = chamfer + FSCORE_W * (1.0f - fscore);
        out[0] = TASK_W * task + DOMAIN_W * (domc / (float)BATCH)
               + (dwc / (float)BATCH);
    }
}

// Arrive on the global counter; last arriver (of NARRIVE) runs the combine.
__device__ __forceinline__ void global_arrive(
    const float* __restrict__ dsw, float* __restrict__ out, int tid)
{
    __threadfence();
    if (tid == 0) {
        int old = atomicAdd(&g_ctr, 1);
        sh_final = (old == NARRIVE - 1) ? 1 : 0;
        if (sh_final) atomicExch(&g_ctr, 0);   // reset for graph replay
    }
    __syncthreads();
    if (sh_final && tid < 32) final_combine(dsw, out, tid);
}

__device__ __forceinline__ void domain_block(
    int b, int tid,
    const float* __restrict__ X,
    const float* __restrict__ W1, const float* __restrict__ b1,
    const float* __restrict__ W2, const float* __restrict__ b2,
    const float* __restrict__ W3, const float* __restrict__ b3,
    const int* __restrict__ labels)
{
    for (int i = tid; i < FDIM; i += TPB) xs[i] = X[b * FDIM + i];
    __syncthreads();
    {   // layer 1: 128 threads x 2 outputs
        float a0 = b1[tid], a1 = b1[tid + 128];
        #pragma unroll 8
        for (int f = 0; f < FDIM; f++) {
            float x = xs[f];
            a0 = fmaf(x, W1[f * H1DIM + tid],       a0);
            a1 = fmaf(x, W1[f * H1DIM + tid + 128], a1);
        }
        h1[tid]       = fmaxf(a0, 0.0f);
        h1[tid + 128] = fmaxf(a1, 0.0f);
    }
    __syncthreads();
    {   // layer 2
        float a = b2[tid];
        #pragma unroll 8
        for (int k = 0; k < H1DIM; k++)
            a = fmaf(h1[k], W2[k * H2DIM + tid], a);
        h2[tid] = fmaxf(a, 0.0f);
    }
    __syncthreads();
    if (tid < DDIM) {
        float a = b3[tid];
        #pragma unroll 8
        for (int k = 0; k < H2DIM; k++)
            a = fmaf(h2[k], W3[k * DDIM + tid], a);
        lg[tid] = a;
    }
    __syncthreads();
    if (tid == 0) {
        float mx = lg[0];
        for (int d = 1; d < DDIM; d++) mx = fmaxf(mx, lg[d]);
        float se = 0.f;
        for (int d = 0; d < DDIM; d++) se += expf(lg[d] - mx);
        g_dom[b] = (mx + logf(se)) - lg[labels[b]];
    }
    __syncthreads();
}

// Single launch: chamfer (y<16), domain MLP (y==16, x==0). Reduction and the
// final combine happen in-kernel via completion counters.
__global__ __launch_bounds__(TPB) void main_kernel(
    const float* __restrict__ P, const float* __restrict__ T,
    const float* __restrict__ X,
    const float* __restrict__ W1, const float* __restrict__ b1,
    const float* __restrict__ W2, const float* __restrict__ b2,
    const float* __restrict__ W3, const float* __restrict__ b3,
    const int* __restrict__ labels,
    const float* __restrict__ dsw, float* __restrict__ out)
{
    const int tid = threadIdx.x;
    const int b   = blockIdx.z;

    if (blockIdx.y == 2 * KSPLIT) {
        if (blockIdx.x == 0) {
            domain_block(b, tid, X, W1, b1, W2, b2, W3, b3, labels);
            global_arrive(dsw, out, tid);
        }
        return;
    }

    const int dir   = blockIdx.y & 1;
    const int split = blockIdx.y >> 1;
    const int qb    = blockIdx.x;
    const int k0    = split * KCHUNK;

    const float* Q = dir ? (T + (size_t)b * NP * 3) : (P + (size_t)b * NP * 3);
    const float* K = dir ? (P + (size_t)b * NP * 3) : (T + (size_t)b * NP * 3);

    unsigned long long qxd[PPT], qyd[PPT], qzd[PPT];
    float q2[PPT], emin[PPT];
    #pragma unroll
    for (int p = 0; p < PPT; p++) {
        int q = qb * QTILE + p * TPB + tid;
        float qx = Q[q * 3 + 0];
        float qy = Q[q * 3 + 1];
        float qz = Q[q * 3 + 2];
        qxd[p] = pack2(qx, qx);
        qyd[p] = pack2(qy, qy);
        qzd[p] = pack2(qz, qz);
        q2[p]  = qx * qx + qy * qy + qz * qz;
        emin[p] = 1e30f;
    }

    const int jo = (tid >> 1) * 4 + (tid & 1);   // packed store offset

    // Prologue: tile 0.
    float kx = K[(k0 + tid) * 3 + 0];
    float ky = K[(k0 + tid) * 3 + 1];
    float kz = K[(k0 + tid) * 3 + 2];
    sA[0][jo]     = -2.0f * kx;
    sA[0][jo + 2] = -2.0f * ky;
    sB[0][jo]     = -2.0f * kz;
    sB[0][jo + 2] = kx * kx + ky * ky + kz * kz;
    __syncthreads();

    for (int t = 0; t < NTILES; t++) {
        const int buf = t & 1;
        if (t + 1 < NTILES) {
            int k = k0 + (t + 1) * KTILE + tid;
            kx = K[k * 3 + 0];
            ky = K[k * 3 + 1];
            kz = K[k * 3 + 2];
        }

        const ulonglong2* pA = (const ulonglong2*)sA[buf];
        const ulonglong2* pB = (const ulonglong2*)sB[buf];
        #pragma unroll 8
        for (int j = 0; j < KTILE / 2; j++) {
            ulonglong2 A = pA[j];   // LDS.128 warp-uniform broadcast
            ulonglong2 B = pB[j];
            #pragma unroll
            for (int p = 0; p < PPT; p++) {
                unsigned long long e = fma2(qxd[p], A.x, B.y);
                e = fma2(qyd[p], A.y, e);
                e = fma2(qzd[p], B.x, e);
                float2 ef = unpack2(e);
                emin[p] = fminf(emin[p], fminf(ef.x, ef.y));
            }
        }

        if (t + 1 < NTILES) {
            const int nbuf = buf ^ 1;
            sA[nbuf][jo]     = -2.0f * kx;
            sA[nbuf][jo + 2] = -2.0f * ky;
            sB[nbuf][jo]     = -2.0f * kz;
            sB[nbuf][jo + 2] = kx * kx + ky * ky + kz * kz;
        }
        __syncthreads();
    }

    #pragma unroll
    for (int p = 0; p < PPT; p++) {
        int q = qb * QTILE + p * TPB + tid;   // coalesced unique store
        g_pmin[dir][b][split][q] = emin[p] + q2[p];
    }

    // ---- group arrive: last of the KSPLIT blocks reduces this q-range ----
    __threadfence();
    if (tid == 0) {
        int old = atomicAdd(&g_ctr_q[dir][b][qb], 1);
        sh_last = (old == KSPLIT - 1) ? 1 : 0;
        if (sh_last) g_ctr_q[dir][b][qb] = 0;   // reset for graph replay
    }
    __syncthreads();
    if (!sh_last) return;

    {
        float sd = 0.f, se = 0.f;
        #pragma unroll
        for (int i = 0; i < PPT; i++) {
            int q = qb * QTILE + i * TPB + tid;   // coalesced across threads
            float m = g_pmin[dir][b][0][q];
            #pragma unroll
            for (int s = 1; s < KSPLIT; s++)
                m = fminf(m, g_pmin[dir][b][s][q]);
            sd += m;
            se += __expf(-m * INV_C);
        }
        #pragma unroll
        for (int s = 16; s > 0; s >>= 1) {
            sd += __shfl_xor_sync(0xffffffffu, sd, s);
            se += __shfl_xor_sync(0xffffffffu, se, s);
        }
        int w = tid >> 5;
        if ((tid & 31) == 0) { red2[w][0] = sd; red2[w][1] = se; }
        __syncthreads();
        if (tid == 0) {
            g_r3[dir][b][qb][0] = red2[0][0] + red2[1][0] + red2[2][0] + red2[3][0];
            g_r3[dir][b][qb][1] = red2[0][1] + red2[1][1] + red2[2][1] + red2[3][1];
        }
    }

    global_arrive(dsw, out, tid);
}

extern "C" void kernel_launch(void* const* d_in, const int* in_sizes, int n_in,
                              void* d_out, int out_size)
{
    const float* pred_pc   = (const float*)d_in[0];
    const float* target_pc = (const float*)d_in[1];
    const float* dfeat     = (const float*)d_in[2];
    const float* dsw       = (const float*)d_in[3];
    const float* W1 = (const float*)d_in[4];
    const float* b1 = (const float*)d_in[5];
    const float* W2 = (const float*)d_in[6];
    const float* b2 = (const float*)d_in[7];
    const float* W3 = (const float*)d_in[8];
    const float* b3 = (const float*)d_in[9];
    const int*   labels = (const int*)d_in[10];
    float* out = (float*)d_out;

    // (4, 17, 8): y<16 chamfer split/dir blocks; y==16,x==0 domain blocks.
    dim3 grid(QB, 2 * KSPLIT + 1, BATCH);
    main_kernel<<<grid, TPB>>>(pred_pc, target_pc, dfeat,
                               W1, b1, W2, b2, W3, b3, labels, dsw, out);
}